// round 4
// baseline (speedup 1.0000x reference)
#include <cuda_runtime.h>

#define Bsz 32
#define Tenc 400
#define Hd 512
#define Lsteps 100
#define Vout 511
#define KS 15

// ---------------- persistent state ------------------------------------------
__device__ float g_hx[2][Bsz * Hd];
__device__ float g_sx[Bsz * Hd];
__device__ float g_scores[Bsz * Tenc];

__device__ __forceinline__ float warp_sum(float v) {
    #pragma unroll
    for (int o = 16; o; o >>= 1) v += __shfl_xor_sync(0xffffffffu, v, o);
    return v;
}
__device__ __forceinline__ float warp_max(float v) {
    #pragma unroll
    for (int o = 16; o; o >>= 1) v = fmaxf(v, __shfl_xor_sync(0xffffffffu, v, o));
    return v;
}

__global__ void zero_hx_kernel() {
    g_hx[0][blockIdx.x * blockDim.x + threadIdx.x] = 0.0f;
}

// ---------------- K1: GRU (+ fc for previous step), register-cached weights --
// blocks [0,64): GRU. block = h-tile of 8 (1 h per warp). Loops 4 b-groups of 8.
// blocks [64,128): fc(t-1). block = v-tile of 8. Same b-group loop.
__global__ void __launch_bounds__(256, 1) k1_gru_fc(
    const int* __restrict__ y, const float* __restrict__ emb,
    const float* __restrict__ W_ih, const float* __restrict__ W_hh,
    const float* __restrict__ b_ih, const float* __restrict__ b_hh,
    const float* __restrict__ fc_w, const float* __restrict__ fc_b,
    float* __restrict__ out, int t, int rd, int wr)
{
    __shared__ float s_buf[2][8][Hd];   // [0]=ix / fc-in, [1]=hx
    int blk = blockIdx.x;
    int tid = threadIdx.x;
    int w = tid >> 5, lane = tid & 31;

    if (blk < 64) {
        int h = (blk << 3) + w;
        // register weights: lane owns elements [lane*16, lane*16+16)
        float4 wv[6][4];
        {
            const float* rows[6] = {
                W_ih + (size_t)h * Hd,
                W_ih + (size_t)(Hd + h) * Hd,
                W_ih + (size_t)(2 * Hd + h) * Hd,
                W_hh + (size_t)h * Hd,
                W_hh + (size_t)(Hd + h) * Hd,
                W_hh + (size_t)(2 * Hd + h) * Hd };
            #pragma unroll
            for (int g = 0; g < 6; g++)
                #pragma unroll
                for (int j = 0; j < 4; j++)
                    wv[g][j] = ((const float4*)rows[g])[lane * 4 + j];
        }
        float bi0 = b_ih[h], bi1 = b_ih[Hd + h], bi2 = b_ih[2 * Hd + h];
        float bh0 = b_hh[h], bh1 = b_hh[Hd + h], bh2 = b_hh[2 * Hd + h];

        for (int bg = 0; bg < 4; bg++) {
            int b0 = bg << 3;
            __syncthreads();
            for (int idx = tid; idx < 8 * Hd; idx += 256) {
                int bb = idx >> 9, i = idx & 511;
                int b = b0 + bb;
                int tok = y[b * 101 + t];
                float v = emb[(size_t)tok * Hd + i];
                if (t > 0) v += g_sx[b * Hd + i];
                s_buf[0][bb][i] = v;
                s_buf[1][bb][i] = g_hx[rd][b * Hd + i];
            }
            __syncthreads();

            float acc[6][8];
            #pragma unroll
            for (int g = 0; g < 6; g++)
                #pragma unroll
                for (int bb = 0; bb < 8; bb++) acc[g][bb] = 0.0f;

            #pragma unroll
            for (int j = 0; j < 4; j++) {
                #pragma unroll
                for (int bb = 0; bb < 8; bb++) {
                    float4 xi = ((const float4*)s_buf[0][bb])[lane * 4 + j];
                    float4 xh = ((const float4*)s_buf[1][bb])[lane * 4 + j];
                    #pragma unroll
                    for (int g = 0; g < 3; g++) {
                        acc[g][bb] = fmaf(wv[g][j].x, xi.x, acc[g][bb]);
                        acc[g][bb] = fmaf(wv[g][j].y, xi.y, acc[g][bb]);
                        acc[g][bb] = fmaf(wv[g][j].z, xi.z, acc[g][bb]);
                        acc[g][bb] = fmaf(wv[g][j].w, xi.w, acc[g][bb]);
                    }
                    #pragma unroll
                    for (int g = 3; g < 6; g++) {
                        acc[g][bb] = fmaf(wv[g][j].x, xh.x, acc[g][bb]);
                        acc[g][bb] = fmaf(wv[g][j].y, xh.y, acc[g][bb]);
                        acc[g][bb] = fmaf(wv[g][j].z, xh.z, acc[g][bb]);
                        acc[g][bb] = fmaf(wv[g][j].w, xh.w, acc[g][bb]);
                    }
                }
            }
            #pragma unroll
            for (int g = 0; g < 6; g++)
                #pragma unroll
                for (int bb = 0; bb < 8; bb++) acc[g][bb] = warp_sum(acc[g][bb]);

            if (lane < 8) {
                int bb = lane, b = b0 + bb;
                float gr = acc[0][bb] + bi0 + acc[3][bb] + bh0;
                float gz = acc[1][bb] + bi1 + acc[4][bb] + bh1;
                float r = 1.0f / (1.0f + expf(-gr));
                float z = 1.0f / (1.0f + expf(-gz));
                float n = tanhf(acc[2][bb] + bi2 + r * (acc[5][bb] + bh2));
                float hp = s_buf[1][bb][h];
                g_hx[wr][b * Hd + h] = (1.0f - z) * n + z * hp;
            }
        }
    } else {
        if (t == 0) return;
        int v = ((blk - 64) << 3) + w;
        bool active = (v < Vout);
        float4 wf[4];
        const float* fw = fc_w + (size_t)(active ? v : 0) * Hd;
        #pragma unroll
        for (int j = 0; j < 4; j++) wf[j] = ((const float4*)fw)[lane * 4 + j];
        float fbv = active ? fc_b[v] : 0.0f;

        for (int bg = 0; bg < 4; bg++) {
            int b0 = bg << 3;
            __syncthreads();
            for (int idx = tid; idx < 8 * Hd; idx += 256) {
                int bb = idx >> 9, i = idx & 511;
                int b = b0 + bb;
                s_buf[0][bb][i] = g_hx[rd][b * Hd + i] + g_sx[b * Hd + i];
            }
            __syncthreads();

            float acc[8];
            #pragma unroll
            for (int bb = 0; bb < 8; bb++) acc[bb] = 0.0f;
            #pragma unroll
            for (int j = 0; j < 4; j++) {
                #pragma unroll
                for (int bb = 0; bb < 8; bb++) {
                    float4 xi = ((const float4*)s_buf[0][bb])[lane * 4 + j];
                    acc[bb] = fmaf(wf[j].x, xi.x, acc[bb]);
                    acc[bb] = fmaf(wf[j].y, xi.y, acc[bb]);
                    acc[bb] = fmaf(wf[j].z, xi.z, acc[bb]);
                    acc[bb] = fmaf(wf[j].w, xi.w, acc[bb]);
                }
            }
            #pragma unroll
            for (int bb = 0; bb < 8; bb++) acc[bb] = warp_sum(acc[bb]);
            if (active && lane < 8) {
                int b = b0 + lane;
                out[(size_t)b * Lsteps * Vout + (size_t)(t - 1) * Vout + v] =
                    acc[lane] + fbv;
            }
        }
    }
}

// ---------------- K2: attention scores ---------------------------------------
// grid 128 = (b, t-tile of 100). block 512 = 16 warps over h. Loads batched x10.
__global__ void __launch_bounds__(512, 1) k2_score(
    const float* __restrict__ x, const float* __restrict__ conv_w,
    const float* __restrict__ conv_b, const float* __restrict__ attn_w,
    const float* __restrict__ attn_b, const float* __restrict__ aligns,
    int t, int wr)
{
    __shared__ float s_win[128];
    __shared__ float s_part[16][100];

    int b  = blockIdx.x >> 2;
    int T0 = (blockIdx.x & 3) * 100;
    int tid = threadIdx.x, c = tid >> 5, lane = tid & 31;
    int h = (c << 5) + lane;

    if (tid < 114) {
        int j = T0 - 7 + tid;
        float v = 0.0f;
        if (t > 0 && j >= 0 && j < Tenc)
            v = aligns[(size_t)b * Lsteps * Tenc + (size_t)(t - 1) * Tenc + j];
        s_win[tid] = v;
    }

    float cw[KS];
    #pragma unroll
    for (int k = 0; k < KS; k++) cw[k] = conv_w[h * KS + k];
    float cbv   = conv_b[h];
    float attwv = attn_w[h];
    float hxv   = g_hx[wr][b * Hd + h];
    __syncthreads();

    const float* xb = x + (size_t)b * Tenc * Hd + h;

    #pragma unroll 1
    for (int tc = 0; tc < 10; tc++) {
        int tl0 = tc * 10;
        float xv[10];
        #pragma unroll
        for (int i = 0; i < 10; i++)
            xv[i] = xb[(size_t)(T0 + tl0 + i) * Hd];
        float wvr[24];
        #pragma unroll
        for (int j = 0; j < 24; j++) wvr[j] = s_win[tl0 + j];

        float part[10];
        #pragma unroll
        for (int i = 0; i < 10; i++) {
            float p = xv[i] + hxv;
            if (t > 0) {
                float conv = cbv;
                #pragma unroll
                for (int k = 0; k < KS; k++)
                    conv = fmaf(cw[k], wvr[i + k], conv);
                p += conv;
            }
            part[i] = fmaxf(p, 0.0f) * attwv;
        }
        #pragma unroll
        for (int i = 0; i < 10; i++) part[i] = warp_sum(part[i]);
        if (lane == 0) {
            #pragma unroll
            for (int i = 0; i < 10; i++) s_part[c][tl0 + i] = part[i];
        }
    }
    __syncthreads();
    if (tid < 100) {
        float s = 0.0f;
        #pragma unroll
        for (int c2 = 0; c2 < 16; c2++) s += s_part[c2][tid];
        g_scores[b * Tenc + T0 + tid] = s + attn_b[0];
    }
}

// ---------------- K3: softmax + context (float4, deep MLP) -------------------
// grid 128 = (b, h-tile of 128). block 512 = 16 t-groups x 32 float4-lanes.
__global__ void __launch_bounds__(512, 1) k3_ctx(
    const float* __restrict__ x, float* __restrict__ aligns, int t)
{
    __shared__ float  s_a[Tenc];
    __shared__ float  s_red[16];
    __shared__ float4 s_ctx[16][32];

    int b  = blockIdx.x >> 2;
    int ht = blockIdx.x & 3;
    int h0 = ht << 7;
    int tid = threadIdx.x, lane = tid & 31, w = tid >> 5;

    float sv = (tid < Tenc) ? g_scores[b * Tenc + tid] : -1e30f;
    float m = warp_max(sv);
    if (lane == 0) s_red[w] = m;
    __syncthreads();
    float bm = -1e30f;
    #pragma unroll
    for (int j = 0; j < 16; j++) bm = fmaxf(bm, s_red[j]);

    float e = (tid < Tenc) ? __expf(sv - bm) : 0.0f;
    if (tid < Tenc) s_a[tid] = e;
    float sum = warp_sum(e);
    __syncthreads();
    if (lane == 0) s_red[w] = sum;
    __syncthreads();
    float tot = 0.0f;
    #pragma unroll
    for (int j = 0; j < 16; j++) tot += s_red[j];
    float inv = 1.0f / tot;

    // context: group w handles t in [w*25, w*25+25), lane owns float4 at h0+lane*4
    const float4* xb4 = (const float4*)(x + (size_t)b * Tenc * Hd) + (h0 >> 2) + lane;
    int t0 = w * 25;
    float4 acc[5];
    #pragma unroll
    for (int j = 0; j < 5; j++) acc[j] = make_float4(0.f, 0.f, 0.f, 0.f);
    #pragma unroll
    for (int i = 0; i < 25; i++) {
        int tt = t0 + i;
        float a = s_a[tt];
        float4 xv = xb4[(size_t)tt * (Hd / 4)];
        float4& A = acc[i % 5];
        A.x = fmaf(a, xv.x, A.x);
        A.y = fmaf(a, xv.y, A.y);
        A.z = fmaf(a, xv.z, A.z);
        A.w = fmaf(a, xv.w, A.w);
    }
    float4 r = acc[0];
    #pragma unroll
    for (int j = 1; j < 5; j++) {
        r.x += acc[j].x; r.y += acc[j].y; r.z += acc[j].z; r.w += acc[j].w;
    }
    s_ctx[w][lane] = r;
    __syncthreads();
    if (tid < 32) {
        float4 a2 = make_float4(0.f, 0.f, 0.f, 0.f);
        #pragma unroll
        for (int g = 0; g < 16; g++) {
            float4 v = s_ctx[g][tid];
            a2.x += v.x; a2.y += v.y; a2.z += v.z; a2.w += v.w;
        }
        a2.x *= inv; a2.y *= inv; a2.z *= inv; a2.w *= inv;
        *(float4*)(g_sx + b * Hd + h0 + tid * 4) = a2;
    }
    if (ht == 0 && tid < Tenc)
        aligns[(size_t)b * Lsteps * Tenc + (size_t)t * Tenc + tid] = s_a[tid] * inv;
}

// ---------------- final fc (step 99) -----------------------------------------
__global__ void k_fc_final(const float* __restrict__ fc_w, const float* __restrict__ fc_b,
                           float* __restrict__ out, int step, int rd)
{
    __shared__ float s_in[8][Hd];
    int fb = blockIdx.x;
    int vt = fb >> 2, bt = fb & 3;
    int b0 = bt << 3;
    int tid = threadIdx.x, w = tid >> 5, lane = tid & 31;
    for (int idx = tid; idx < 8 * Hd; idx += 256) {
        int bb = idx >> 9, i = idx & 511;
        int b = b0 + bb;
        s_in[bb][i] = g_hx[rd][b * Hd + i] + g_sx[b * Hd + i];
    }
    __syncthreads();
    int v = (vt << 3) + w;
    if (v >= Vout) return;
    const float* fw = fc_w + (size_t)v * Hd;
    float acc[8];
    #pragma unroll
    for (int bb = 0; bb < 8; bb++) acc[bb] = 0.0f;
    for (int i = lane; i < Hd; i += 32) {
        float wv = fw[i];
        #pragma unroll
        for (int bb = 0; bb < 8; bb++) acc[bb] = fmaf(wv, s_in[bb][i], acc[bb]);
    }
    #pragma unroll
    for (int bb = 0; bb < 8; bb++) acc[bb] = warp_sum(acc[bb]);
    if (lane < 8) {
        int b = b0 + lane;
        out[(size_t)b * Lsteps * Vout + (size_t)step * Vout + v] = acc[lane] + fc_b[v];
    }
}

// ---------------- launch ------------------------------------------------------
extern "C" void kernel_launch(void* const* d_in, const int* in_sizes, int n_in,
                              void* d_out, int out_size)
{
    const float* x      = (const float*)d_in[0];
    const int*   y      = (const int*)  d_in[1];
    const float* emb    = (const float*)d_in[2];
    const float* W_ih   = (const float*)d_in[3];
    const float* W_hh   = (const float*)d_in[4];
    const float* b_ih   = (const float*)d_in[5];
    const float* b_hh   = (const float*)d_in[6];
    const float* conv_w = (const float*)d_in[7];
    const float* conv_b = (const float*)d_in[8];
    const float* attn_w = (const float*)d_in[9];
    const float* attn_b = (const float*)d_in[10];
    const float* fc_w   = (const float*)d_in[11];
    const float* fc_b   = (const float*)d_in[12];

    float* out    = (float*)d_out;
    float* aligns = out + (size_t)Bsz * Lsteps * Vout;

    zero_hx_kernel<<<32, 512>>>();

    for (int t = 0; t < Lsteps; t++) {
        int rd = t & 1;
        int wr = rd ^ 1;
        k1_gru_fc<<<128, 256>>>(y, emb, W_ih, W_hh, b_ih, b_hh, fc_w, fc_b,
                                out, t, rd, wr);
        k2_score<<<128, 512>>>(x, conv_w, conv_b, attn_w, attn_b, aligns, t, wr);
        k3_ctx<<<128, 512>>>(x, aligns, t);
    }
    // hx of step 99 lives in buffer 0
    k_fc_final<<<256, 256>>>(fc_w, fc_b, out, Lsteps - 1, 0);
}

// round 5
// speedup vs baseline: 1.4000x; 1.4000x over previous
#include <cuda_runtime.h>

#define Bsz 32
#define Tenc 400
#define Hd 512
#define Lsteps 100
#define Vout 511
#define KS 15

// ---------------- persistent state ------------------------------------------
__device__ float g_hx[2][Bsz * Hd];
__device__ float g_sx[Bsz * Hd];
__device__ float g_scores[Bsz * Tenc];

__device__ __forceinline__ float warp_sum(float v) {
    #pragma unroll
    for (int o = 16; o; o >>= 1) v += __shfl_xor_sync(0xffffffffu, v, o);
    return v;
}
__device__ __forceinline__ float warp_max(float v) {
    #pragma unroll
    for (int o = 16; o; o >>= 1) v = fmaxf(v, __shfl_xor_sync(0xffffffffu, v, o));
    return v;
}

__global__ void zero_hx_kernel() {
    g_hx[0][blockIdx.x * blockDim.x + threadIdx.x] = 0.0f;
}

// ---------------- K1: GRU cell (+ fc for previous step) ---------------------
// blocks [0,256): GRU. block = (h-tile of 8, b-tile of 8). warp = 1 h, 8 b.
// blocks [256,512): fc for step t-1. block = (v-tile of 8, b-tile of 8).
__global__ void k1_gru_fc(
    const int* __restrict__ y, const float* __restrict__ emb,
    const float* __restrict__ W_ih, const float* __restrict__ W_hh,
    const float* __restrict__ b_ih, const float* __restrict__ b_hh,
    const float* __restrict__ fc_w, const float* __restrict__ fc_b,
    float* __restrict__ out, int t, int rd, int wr)
{
    __shared__ float s_buf[2][8][Hd];   // [0]=ix / fc-in, [1]=hx
    int blk = blockIdx.x;
    int tid = threadIdx.x;
    int w = tid >> 5, lane = tid & 31;

    if (blk < 256) {
        int ht = blk >> 2, bt = blk & 3;
        int h0 = ht << 3, b0 = bt << 3;
        for (int idx = tid; idx < 8 * Hd; idx += 256) {
            int bb = idx >> 9, i = idx & 511;
            int b = b0 + bb;
            int tok = y[b * 101 + t];
            float v = emb[(size_t)tok * Hd + i];
            if (t > 0) v += g_sx[b * Hd + i];
            s_buf[0][bb][i] = v;
            s_buf[1][bb][i] = g_hx[rd][b * Hd + i];
        }
        __syncthreads();

        int h = h0 + w;
        const float* wi0 = W_ih + (size_t)h * Hd;
        const float* wi1 = W_ih + (size_t)(Hd + h) * Hd;
        const float* wi2 = W_ih + (size_t)(2 * Hd + h) * Hd;
        const float* wh0 = W_hh + (size_t)h * Hd;
        const float* wh1 = W_hh + (size_t)(Hd + h) * Hd;
        const float* wh2 = W_hh + (size_t)(2 * Hd + h) * Hd;

        float acc[6][8];
        #pragma unroll
        for (int g = 0; g < 6; g++)
            #pragma unroll
            for (int bb = 0; bb < 8; bb++) acc[g][bb] = 0.0f;

        for (int i = lane; i < Hd; i += 32) {
            float w0 = wi0[i], w1 = wi1[i], w2 = wi2[i];
            float w3 = wh0[i], w4 = wh1[i], w5 = wh2[i];
            #pragma unroll
            for (int bb = 0; bb < 8; bb++) {
                float xi = s_buf[0][bb][i];
                float xh = s_buf[1][bb][i];
                acc[0][bb] = fmaf(w0, xi, acc[0][bb]);
                acc[1][bb] = fmaf(w1, xi, acc[1][bb]);
                acc[2][bb] = fmaf(w2, xi, acc[2][bb]);
                acc[3][bb] = fmaf(w3, xh, acc[3][bb]);
                acc[4][bb] = fmaf(w4, xh, acc[4][bb]);
                acc[5][bb] = fmaf(w5, xh, acc[5][bb]);
            }
        }
        #pragma unroll
        for (int g = 0; g < 6; g++)
            #pragma unroll
            for (int bb = 0; bb < 8; bb++) acc[g][bb] = warp_sum(acc[g][bb]);

        if (lane < 8) {
            int bb = lane, b = b0 + bb;
            float gr = acc[0][bb] + b_ih[h] + acc[3][bb] + b_hh[h];
            float gz = acc[1][bb] + b_ih[Hd + h] + acc[4][bb] + b_hh[Hd + h];
            float r = 1.0f / (1.0f + expf(-gr));
            float z = 1.0f / (1.0f + expf(-gz));
            float n = tanhf(acc[2][bb] + b_ih[2 * Hd + h] +
                            r * (acc[5][bb] + b_hh[2 * Hd + h]));
            float hp = s_buf[1][bb][h];
            g_hx[wr][b * Hd + h] = (1.0f - z) * n + z * hp;
        }
    } else {
        if (t == 0) return;
        int fb = blk - 256;
        int vt = fb >> 2, bt = fb & 3;
        int b0 = bt << 3;
        for (int idx = tid; idx < 8 * Hd; idx += 256) {
            int bb = idx >> 9, i = idx & 511;
            int b = b0 + bb;
            s_buf[0][bb][i] = g_hx[rd][b * Hd + i] + g_sx[b * Hd + i];
        }
        __syncthreads();

        int v = (vt << 3) + w;
        if (v >= Vout) return;
        const float* fw = fc_w + (size_t)v * Hd;
        float acc[8];
        #pragma unroll
        for (int bb = 0; bb < 8; bb++) acc[bb] = 0.0f;
        for (int i = lane; i < Hd; i += 32) {
            float wv = fw[i];
            #pragma unroll
            for (int bb = 0; bb < 8; bb++)
                acc[bb] = fmaf(wv, s_buf[0][bb][i], acc[bb]);
        }
        #pragma unroll
        for (int bb = 0; bb < 8; bb++) acc[bb] = warp_sum(acc[bb]);
        if (lane < 8) {
            int b = b0 + lane;
            out[(size_t)b * Lsteps * Vout + (size_t)(t - 1) * Vout + v] =
                acc[lane] + fc_b[v];
        }
    }
}

// ---------------- K2: attention scores ---------------------------------------
// grid 256 = (b, t-tile of 50). block 512 = 16 warps over h.
// conv_w row + window in registers; x loads batched x10 for MLP.
__global__ void __launch_bounds__(512, 1) k2_score(
    const float* __restrict__ x, const float* __restrict__ conv_w,
    const float* __restrict__ conv_b, const float* __restrict__ attn_w,
    const float* __restrict__ attn_b, const float* __restrict__ aligns,
    int t, int wr)
{
    __shared__ float s_win[64];
    __shared__ float s_part[16][50];

    int b  = blockIdx.x >> 3;
    int tb = blockIdx.x & 7;
    int T0 = tb * 50;
    int tid = threadIdx.x, c = tid >> 5, lane = tid & 31;
    int h = (c << 5) + lane;

    if (tid < 64) {
        int j = T0 - 7 + tid;
        float v = 0.0f;
        if (t > 0 && j >= 0 && j < Tenc)
            v = aligns[(size_t)b * Lsteps * Tenc + (size_t)(t - 1) * Tenc + j];
        s_win[tid] = v;
    }

    float cw[KS];
    #pragma unroll
    for (int k = 0; k < KS; k++) cw[k] = conv_w[h * KS + k];
    float cbv   = conv_b[h];
    float attwv = attn_w[h];
    float hxv   = g_hx[wr][b * Hd + h];
    __syncthreads();

    const float* xb = x + (size_t)b * Tenc * Hd + h;

    #pragma unroll 1
    for (int tc = 0; tc < 5; tc++) {
        int tl0 = tc * 10;
        float xv[10];
        #pragma unroll
        for (int i = 0; i < 10; i++)
            xv[i] = xb[(size_t)(T0 + tl0 + i) * Hd];
        float wvr[24];
        #pragma unroll
        for (int j = 0; j < 24; j++) wvr[j] = s_win[tl0 + j];

        float part[10];
        #pragma unroll
        for (int i = 0; i < 10; i++) {
            float p = xv[i] + hxv;
            if (t > 0) {
                float conv = cbv;
                #pragma unroll
                for (int k = 0; k < KS; k++)
                    conv = fmaf(cw[k], wvr[i + k], conv);
                p += conv;
            }
            part[i] = fmaxf(p, 0.0f) * attwv;
        }
        #pragma unroll
        for (int i = 0; i < 10; i++) part[i] = warp_sum(part[i]);
        if (lane == 0) {
            #pragma unroll
            for (int i = 0; i < 10; i++) s_part[c][tl0 + i] = part[i];
        }
    }
    __syncthreads();
    if (tid < 50) {
        float s = 0.0f;
        #pragma unroll
        for (int c2 = 0; c2 < 16; c2++) s += s_part[c2][tid];
        g_scores[b * Tenc + T0 + tid] = s + attn_b[0];
    }
}

// ---------------- K3: softmax + context (float4, deep MLP) -------------------
// grid 128 = (b, h-tile of 128). block 512 = 16 t-groups x 32 float4-lanes.
__global__ void __launch_bounds__(512, 1) k3_ctx(
    const float* __restrict__ x, float* __restrict__ aligns, int t)
{
    __shared__ float  s_a[Tenc];
    __shared__ float  s_red[16];
    __shared__ float4 s_ctx[16][32];

    int b  = blockIdx.x >> 2;
    int ht = blockIdx.x & 3;
    int h0 = ht << 7;
    int tid = threadIdx.x, lane = tid & 31, w = tid >> 5;

    float sv = (tid < Tenc) ? g_scores[b * Tenc + tid] : -1e30f;
    float m = warp_max(sv);
    if (lane == 0) s_red[w] = m;
    __syncthreads();
    float bm = -1e30f;
    #pragma unroll
    for (int j = 0; j < 16; j++) bm = fmaxf(bm, s_red[j]);

    float e = (tid < Tenc) ? __expf(sv - bm) : 0.0f;
    if (tid < Tenc) s_a[tid] = e;
    float sum = warp_sum(e);
    __syncthreads();
    if (lane == 0) s_red[w] = sum;
    __syncthreads();
    float tot = 0.0f;
    #pragma unroll
    for (int j = 0; j < 16; j++) tot += s_red[j];
    float inv = 1.0f / tot;

    // context: group w handles t in [w*25, w*25+25), lane owns float4 at h0+lane*4
    const float4* xb4 = (const float4*)(x + (size_t)b * Tenc * Hd) + (h0 >> 2) + lane;
    int t0 = w * 25;
    float4 acc[5];
    #pragma unroll
    for (int j = 0; j < 5; j++) acc[j] = make_float4(0.f, 0.f, 0.f, 0.f);
    #pragma unroll
    for (int i = 0; i < 25; i++) {
        int tt = t0 + i;
        float a = s_a[tt];
        float4 xv = xb4[(size_t)tt * (Hd / 4)];
        float4& A = acc[i % 5];
        A.x = fmaf(a, xv.x, A.x);
        A.y = fmaf(a, xv.y, A.y);
        A.z = fmaf(a, xv.z, A.z);
        A.w = fmaf(a, xv.w, A.w);
    }
    float4 r = acc[0];
    #pragma unroll
    for (int j = 1; j < 5; j++) {
        r.x += acc[j].x; r.y += acc[j].y; r.z += acc[j].z; r.w += acc[j].w;
    }
    s_ctx[w][lane] = r;
    __syncthreads();
    if (tid < 32) {
        float4 a2 = make_float4(0.f, 0.f, 0.f, 0.f);
        #pragma unroll
        for (int g = 0; g < 16; g++) {
            float4 v = s_ctx[g][tid];
            a2.x += v.x; a2.y += v.y; a2.z += v.z; a2.w += v.w;
        }
        a2.x *= inv; a2.y *= inv; a2.z *= inv; a2.w *= inv;
        *(float4*)(g_sx + b * Hd + h0 + tid * 4) = a2;
    }
    if (ht == 0 && tid < Tenc)
        aligns[(size_t)b * Lsteps * Tenc + (size_t)t * Tenc + tid] = s_a[tid] * inv;
}

// ---------------- final fc (step 99) -----------------------------------------
__global__ void k_fc_final(const float* __restrict__ fc_w, const float* __restrict__ fc_b,
                           float* __restrict__ out, int step, int rd)
{
    __shared__ float s_in[8][Hd];
    int fb = blockIdx.x;
    int vt = fb >> 2, bt = fb & 3;
    int b0 = bt << 3;
    int tid = threadIdx.x, w = tid >> 5, lane = tid & 31;
    for (int idx = tid; idx < 8 * Hd; idx += 256) {
        int bb = idx >> 9, i = idx & 511;
        int b = b0 + bb;
        s_in[bb][i] = g_hx[rd][b * Hd + i] + g_sx[b * Hd + i];
    }
    __syncthreads();
    int v = (vt << 3) + w;
    if (v >= Vout) return;
    const float* fw = fc_w + (size_t)v * Hd;
    float acc[8];
    #pragma unroll
    for (int bb = 0; bb < 8; bb++) acc[bb] = 0.0f;
    for (int i = lane; i < Hd; i += 32) {
        float wv = fw[i];
        #pragma unroll
        for (int bb = 0; bb < 8; bb++) acc[bb] = fmaf(wv, s_in[bb][i], acc[bb]);
    }
    #pragma unroll
    for (int bb = 0; bb < 8; bb++) acc[bb] = warp_sum(acc[bb]);
    if (lane < 8) {
        int b = b0 + lane;
        out[(size_t)b * Lsteps * Vout + (size_t)step * Vout + v] = acc[lane] + fc_b[v];
    }
}

// ---------------- launch ------------------------------------------------------
extern "C" void kernel_launch(void* const* d_in, const int* in_sizes, int n_in,
                              void* d_out, int out_size)
{
    const float* x      = (const float*)d_in[0];
    const int*   y      = (const int*)  d_in[1];
    const float* emb    = (const float*)d_in[2];
    const float* W_ih   = (const float*)d_in[3];
    const float* W_hh   = (const float*)d_in[4];
    const float* b_ih   = (const float*)d_in[5];
    const float* b_hh   = (const float*)d_in[6];
    const float* conv_w = (const float*)d_in[7];
    const float* conv_b = (const float*)d_in[8];
    const float* attn_w = (const float*)d_in[9];
    const float* attn_b = (const float*)d_in[10];
    const float* fc_w   = (const float*)d_in[11];
    const float* fc_b   = (const float*)d_in[12];

    float* out    = (float*)d_out;
    float* aligns = out + (size_t)Bsz * Lsteps * Vout;

    zero_hx_kernel<<<32, 512>>>();

    for (int t = 0; t < Lsteps; t++) {
        int rd = t & 1;
        int wr = rd ^ 1;
        k1_gru_fc<<<512, 256>>>(y, emb, W_ih, W_hh, b_ih, b_hh, fc_w, fc_b,
                                out, t, rd, wr);
        k2_score<<<256, 512>>>(x, conv_w, conv_b, attn_w, attn_b, aligns, t, wr);
        k3_ctx<<<128, 512>>>(x, aligns, t);
    }
    // hx of step 99 lives in buffer 0
    k_fc_final<<<256, 256>>>(fc_w, fc_b, out, Lsteps - 1, 0);
}